// round 1
// baseline (speedup 1.0000x reference)
#include <cuda_runtime.h>
#include <cuda_bf16.h>

// Problem constants (fixed by dataset)
constexpr int DMAX  = 128;      // representation dim
constexpr int NMAX  = 50000;    // predictions

// Scratch (allocation-free rule: __device__ globals)
__device__ float g_P[(size_t)NMAX * DMAX];       // precomputed feats @ Wb_D + bb
__device__ float g_pooled[(size_t)NMAX * DMAX];  // segment-max pool
__device__ float g_x1[(size_t)NMAX * DMAX];      // block-0 output
__device__ float g_x2[(size_t)NMAX * DMAX];      // block-1 output

// ---------------------------------------------------------------------------
// GEMM: C[n][j] = (RES ? R[n][j] : 0) + sum_k A[n][k] * W[k][j] + bias[j]
// A: Nrows x 128 row-major, W: 128 x 128 row-major (top 128 rows of Wb, or Wo)
// CTA: 256 threads, 64 rows x 128 cols tile. Thread: 8 rows x 4 cols.
// ---------------------------------------------------------------------------
template <bool RES>
__global__ void gemm128_kernel(const float* __restrict__ A,
                               const float* __restrict__ W,
                               const float* __restrict__ bias,
                               const float* __restrict__ R,
                               float* __restrict__ C, int Nrows) {
    __shared__ float As[64][32];    // A tile (k-chunk)
    __shared__ float Ws[32][128];   // W tile (k-chunk)

    const int tid = threadIdx.x;
    const int tx = tid & 31;        // column group: cols [4*tx, 4*tx+4)
    const int ty = tid >> 5;        // row group: rows [ty*8, ty*8+8) within tile
    const int row0 = blockIdx.x * 64;

    float acc[8][4];
#pragma unroll
    for (int r = 0; r < 8; r++)
#pragma unroll
        for (int c = 0; c < 4; c++) acc[r][c] = 0.0f;

    for (int k0 = 0; k0 < 128; k0 += 32) {
        // Load W chunk: 32x128 = 1024 float4, 4 per thread.
#pragma unroll
        for (int i = 0; i < 4; i++) {
            int idx = tid + i * 256;          // float4 index
            int kr = idx >> 5;                // row in chunk
            int jc = idx & 31;                // float4 col
            reinterpret_cast<float4*>(Ws)[idx] =
                reinterpret_cast<const float4*>(W + (size_t)(k0 + kr) * 128)[jc];
        }
        // Load A chunk: 64x32 = 512 float4, 2 per thread.
#pragma unroll
        for (int i = 0; i < 2; i++) {
            int idx = tid + i * 256;
            int r = idx >> 3;                 // row in tile (8 float4 per row)
            int jc = idx & 7;
            float4 v = make_float4(0.f, 0.f, 0.f, 0.f);
            if (row0 + r < Nrows)
                v = reinterpret_cast<const float4*>(A + (size_t)(row0 + r) * 128 + k0)[jc];
            reinterpret_cast<float4*>(As)[idx] = v;
        }
        __syncthreads();

#pragma unroll
        for (int kk = 0; kk < 32; kk++) {
            float4 b4 = reinterpret_cast<float4*>(Ws[kk])[tx];
#pragma unroll
            for (int rr = 0; rr < 8; rr++) {
                float a = As[ty * 8 + rr][kk];   // broadcast within warp
                acc[rr][0] = fmaf(a, b4.x, acc[rr][0]);
                acc[rr][1] = fmaf(a, b4.y, acc[rr][1]);
                acc[rr][2] = fmaf(a, b4.z, acc[rr][2]);
                acc[rr][3] = fmaf(a, b4.w, acc[rr][3]);
            }
        }
        __syncthreads();
    }

    float4 bv = reinterpret_cast<const float4*>(bias)[tx];
#pragma unroll
    for (int rr = 0; rr < 8; rr++) {
        int r = row0 + ty * 8 + rr;
        if (r < Nrows) {
            float4 o;
            o.x = acc[rr][0] + bv.x;
            o.y = acc[rr][1] + bv.y;
            o.z = acc[rr][2] + bv.z;
            o.w = acc[rr][3] + bv.w;
            if (RES) {
                float4 rv = reinterpret_cast<const float4*>(R + (size_t)r * 128)[tx];
                o.x += rv.x; o.y += rv.y; o.z += rv.z; o.w += rv.w;
            }
            reinterpret_cast<float4*>(C + (size_t)r * 128)[tx] = o;
        }
    }
}

// ---------------------------------------------------------------------------
// Edge kernel: for each edge e,
//   h[e][:] = relu( P[nb[e]][:] + sum_a add_info[e][a] * Wba[a][:] )
//   pooled[seg[e]][:] = max(pooled, h)     (seg sorted -> register run-max)
// One warp handles 32 contiguous edges; 4 cols per lane (float4).
// atomicMax on int bits is exact for nonnegative floats (relu output, init 0).
// ---------------------------------------------------------------------------
__device__ __forceinline__ void flush_max(float* pooled, int seg, int lane, float4 v) {
    if (seg < 0) return;
    int* p = reinterpret_cast<int*>(pooled + (size_t)seg * 128 + lane * 4);
    if (v.x > 0.f) atomicMax(p + 0, __float_as_int(v.x));
    if (v.y > 0.f) atomicMax(p + 1, __float_as_int(v.y));
    if (v.z > 0.f) atomicMax(p + 2, __float_as_int(v.z));
    if (v.w > 0.f) atomicMax(p + 3, __float_as_int(v.w));
}

constexpr int EDGES_PER_WARP = 32;

__global__ void edge_kernel(const float* __restrict__ P,
                            const float4* __restrict__ ai,       // add_info as float4
                            const int* __restrict__ nb,
                            const int* __restrict__ seg,
                            const float* __restrict__ Wba,       // 4 x 128 (rows 128..131 of Wb)
                            float* __restrict__ pooled, int E) {
    __shared__ float4 wsh[4 * 32];
    const int tid = threadIdx.x;
    if (tid < 128) wsh[tid] = reinterpret_cast<const float4*>(Wba)[tid];
    __syncthreads();

    const int lane = tid & 31;
    const int warp = tid >> 5;
    const float4 w0 = wsh[0 * 32 + lane];
    const float4 w1 = wsh[1 * 32 + lane];
    const float4 w2 = wsh[2 * 32 + lane];
    const float4 w3 = wsh[3 * 32 + lane];

    const int base = (blockIdx.x * (blockDim.x >> 5) + warp) * EDGES_PER_WARP;
    if (base >= E) return;
    const int end = min(base + EDGES_PER_WARP, E);

    float4 vmax = make_float4(0.f, 0.f, 0.f, 0.f);
    int cur = -1;

    for (int e = base; e < end; e++) {
        int s = __ldg(seg + e);
        int n = __ldg(nb + e);
        float4 p = __ldg(reinterpret_cast<const float4*>(P) + (size_t)n * 32 + lane);
        float4 a = __ldg(ai + e);

        float4 h;
        h.x = fmaxf(fmaf(a.x, w0.x, fmaf(a.y, w1.x, fmaf(a.z, w2.x, fmaf(a.w, w3.x, p.x)))), 0.f);
        h.y = fmaxf(fmaf(a.x, w0.y, fmaf(a.y, w1.y, fmaf(a.z, w2.y, fmaf(a.w, w3.y, p.y)))), 0.f);
        h.z = fmaxf(fmaf(a.x, w0.z, fmaf(a.y, w1.z, fmaf(a.z, w2.z, fmaf(a.w, w3.z, p.z)))), 0.f);
        h.w = fmaxf(fmaf(a.x, w0.w, fmaf(a.y, w1.w, fmaf(a.z, w2.w, fmaf(a.w, w3.w, p.w)))), 0.f);

        if (s != cur) {                 // warp-uniform branch (s uniform across warp)
            flush_max(pooled, cur, lane, vmax);
            cur = s;
            vmax = h;
        } else {
            vmax.x = fmaxf(vmax.x, h.x);
            vmax.y = fmaxf(vmax.y, h.y);
            vmax.z = fmaxf(vmax.z, h.z);
            vmax.w = fmaxf(vmax.w, h.w);
        }
    }
    flush_max(pooled, cur, lane, vmax);
}

// ---------------------------------------------------------------------------
// Final: out[n] = x[n] . Wf + bf      (one warp per row)
// ---------------------------------------------------------------------------
__global__ void final_kernel(const float* __restrict__ x,
                             const float* __restrict__ Wf,
                             const float* __restrict__ bf,
                             float* __restrict__ out, int N) {
    int gwarp = (blockIdx.x * blockDim.x + threadIdx.x) >> 5;
    int lane = threadIdx.x & 31;
    if (gwarp >= N) return;
    float4 xv = reinterpret_cast<const float4*>(x + (size_t)gwarp * 128)[lane];
    float4 wv = reinterpret_cast<const float4*>(Wf)[lane];
    float s = xv.x * wv.x + xv.y * wv.y + xv.z * wv.z + xv.w * wv.w;
#pragma unroll
    for (int o = 16; o; o >>= 1) s += __shfl_xor_sync(0xFFFFFFFFu, s, o);
    if (lane == 0) out[gwarp] = s + bf[0];
}

// ---------------------------------------------------------------------------
extern "C" void kernel_launch(void* const* d_in, const int* in_sizes, int n_in,
                              void* d_out, int out_size) {
    const float* interpolated = (const float*)d_in[0];   // (N,128)
    const float* add_info     = (const float*)d_in[1];   // (E,4)
    const int*   nb           = (const int*)d_in[2];     // (E,)
    const int*   seg          = (const int*)d_in[3];     // (E,) sorted
    const float* Wb0 = (const float*)d_in[4];            // (132,128)
    const float* bb0 = (const float*)d_in[5];
    const float* Wo0 = (const float*)d_in[6];            // (128,128)
    const float* bo0 = (const float*)d_in[7];
    const float* Wb1 = (const float*)d_in[8];
    const float* bb1 = (const float*)d_in[9];
    const float* Wo1 = (const float*)d_in[10];
    const float* bo1 = (const float*)d_in[11];
    const float* Wf  = (const float*)d_in[12];           // (128,1)
    const float* bf  = (const float*)d_in[13];

    const int N = in_sizes[0] / 128;
    const int E = in_sizes[2];

    float *P, *pooled, *x1, *x2;
    cudaGetSymbolAddress((void**)&P,      g_P);
    cudaGetSymbolAddress((void**)&pooled, g_pooled);
    cudaGetSymbolAddress((void**)&x1,     g_x1);
    cudaGetSymbolAddress((void**)&x2,     g_x2);

    const int gemmGrid = (N + 63) / 64;
    const int edgeGrid = (E + 8 * EDGES_PER_WARP - 1) / (8 * EDGES_PER_WARP);
    const size_t poolBytes = (size_t)N * 128 * sizeof(float);
    const float4* ai = (const float4*)add_info;

    // ---- Block 0 ----
    gemm128_kernel<false><<<gemmGrid, 256>>>(interpolated, Wb0, bb0, nullptr, P, N);
    cudaMemsetAsync(pooled, 0, poolBytes);
    edge_kernel<<<edgeGrid, 256>>>(P, ai, nb, seg, Wb0 + 128 * 128, pooled, E);
    gemm128_kernel<true><<<gemmGrid, 256>>>(pooled, Wo0, bo0, interpolated, x1, N);

    // ---- Block 1 ----
    gemm128_kernel<false><<<gemmGrid, 256>>>(x1, Wb1, bb1, nullptr, P, N);
    cudaMemsetAsync(pooled, 0, poolBytes);
    edge_kernel<<<edgeGrid, 256>>>(P, ai, nb, seg, Wb1 + 128 * 128, pooled, E);
    gemm128_kernel<true><<<gemmGrid, 256>>>(pooled, Wo1, bo1, x1, x2, N);

    // ---- Final projection ----
    final_kernel<<<(N * 32 + 255) / 256, 256>>>(x2, Wf, bf, (float*)d_out, N);
}